// round 16
// baseline (speedup 1.0000x reference)
#include <cuda_runtime.h>
#include <cuda_fp16.h>
#include <math.h>
#include <stdint.h>

#define BB   8
#define WLEN 1000
#define EMB  100
#define CC   50
#define LL   18000

#define WPAD 1024
// H: [b][w][k-halves], 64 halves (128B) per w row.
// k>=52 and w>=1000 stay zero; k50 = 1.0 (ones column for d), k51 = 0.
__device__ __align__(16) uint32_t g_Hh[BB * WPAD * 32];

// ===========================================================================
// Kernel 1: embedding + conv1d(k=3,same) + tanh -> g_Hh[b][w][k]
// swizzled emb_s: conflict-free LDS/STS. Also writes ones column at k=50.
// ===========================================================================
#define CT_W    40
#define CT_ROWS (CT_W + 2)

__device__ __forceinline__ float tanh_fast(float x) {
    float y;
    asm("tanh.approx.f32 %0, %1;" : "=f"(y) : "f"(x));
    return y;
}

__global__ __launch_bounds__(256)
void conv_kernel(const int* __restrict__ x, const float* __restrict__ W_embed,
                 const float* __restrict__ conv_w, const float* __restrict__ conv_b) {
    __shared__ __align__(16) float emb_s[CT_ROWS * 128];
    __shared__ int tok_s[CT_ROWS];
    const int b  = blockIdx.y;
    const int w0 = blockIdx.x * CT_W;
    const int tid = threadIdx.x;

    if (tid < CT_ROWS) {
        int w = w0 - 1 + tid;
        tok_s[tid] = (w >= 0 && w < WLEN) ? x[b * WLEN + w] : -1;
    }
    __syncthreads();
    for (int i = tid; i < CT_ROWS * 25; i += 256) {
        int r = i / 25, g = i - r * 25;
        int t = tok_s[r];
        float4 v = make_float4(0.f, 0.f, 0.f, 0.f);
        if (t >= 0) v = *(const float4*)&W_embed[(long)t * EMB + g * 4];
        *(float4*)&emb_s[(r * 32 + (g ^ ((r >> 2) & 7))) * 4] = v;
    }
    __syncthreads();

    if (tid < 250) {
        const int p = tid / 10, q = tid - p * 10;
        const int wl = q * 4;
        const int sw0 = q & 7, sw1 = (q + 1) & 7;
        const int c0 = 2 * p, c1 = 2 * p + 1;
        float acc[2][4];
        float bias0 = conv_b[c0], bias1 = conv_b[c1];
#pragma unroll
        for (int w = 0; w < 4; w++) { acc[0][w] = bias0; acc[1][w] = bias1; }

        const float4* cw0 = (const float4*)(conv_w + c0 * EMB * 3);
        const float4* cw1 = (const float4*)(conv_w + c1 * EMB * 3);

        for (int g = 0; g < 25; g++) {
            float4 v[6];
#pragma unroll
            for (int r = 0; r < 6; r++) {
                int sw = (r < 4) ? sw0 : sw1;
                v[r] = *(const float4*)&emb_s[((wl + r) * 32 + (g ^ sw)) * 4];
            }
            float4 q0 = cw0[g * 3], q1 = cw0[g * 3 + 1], q2 = cw0[g * 3 + 2];
#pragma unroll
            for (int w = 0; w < 4; w++) {
                acc[0][w] = fmaf(v[w].x, q0.x, acc[0][w]);
                acc[0][w] = fmaf(v[w + 1].x, q0.y, acc[0][w]);
                acc[0][w] = fmaf(v[w + 2].x, q0.z, acc[0][w]);
                acc[0][w] = fmaf(v[w].y, q0.w, acc[0][w]);
                acc[0][w] = fmaf(v[w + 1].y, q1.x, acc[0][w]);
                acc[0][w] = fmaf(v[w + 2].y, q1.y, acc[0][w]);
                acc[0][w] = fmaf(v[w].z, q1.z, acc[0][w]);
                acc[0][w] = fmaf(v[w + 1].z, q1.w, acc[0][w]);
                acc[0][w] = fmaf(v[w + 2].z, q2.x, acc[0][w]);
                acc[0][w] = fmaf(v[w].w, q2.y, acc[0][w]);
                acc[0][w] = fmaf(v[w + 1].w, q2.z, acc[0][w]);
                acc[0][w] = fmaf(v[w + 2].w, q2.w, acc[0][w]);
            }
            q0 = cw1[g * 3]; q1 = cw1[g * 3 + 1]; q2 = cw1[g * 3 + 2];
#pragma unroll
            for (int w = 0; w < 4; w++) {
                acc[1][w] = fmaf(v[w].x, q0.x, acc[1][w]);
                acc[1][w] = fmaf(v[w + 1].x, q0.y, acc[1][w]);
                acc[1][w] = fmaf(v[w + 2].x, q0.z, acc[1][w]);
                acc[1][w] = fmaf(v[w].y, q0.w, acc[1][w]);
                acc[1][w] = fmaf(v[w + 1].y, q1.x, acc[1][w]);
                acc[1][w] = fmaf(v[w + 2].y, q1.y, acc[1][w]);
                acc[1][w] = fmaf(v[w].z, q1.z, acc[1][w]);
                acc[1][w] = fmaf(v[w + 1].z, q1.w, acc[1][w]);
                acc[1][w] = fmaf(v[w + 2].z, q2.x, acc[1][w]);
                acc[1][w] = fmaf(v[w].w, q2.y, acc[1][w]);
                acc[1][w] = fmaf(v[w + 1].w, q2.z, acc[1][w]);
                acc[1][w] = fmaf(v[w + 2].w, q2.w, acc[1][w]);
            }
        }
#pragma unroll
        for (int i = 0; i < 4; i++) {
            __half2 h = __floats2half2_rn(tanh_fast(acc[0][i]), tanh_fast(acc[1][i]));
            g_Hh[((b * WPAD) + w0 + wl + i) * 32 + p] = *(uint32_t*)&h;
        }
        if (p == 0) {   // ones column: k50 = 1.0 (half 0x3C00), k51 = 0
#pragma unroll
            for (int i = 0; i < 4; i++)
                g_Hh[((b * WPAD) + w0 + wl + i) * 32 + 25] = 0x00003C00u;
        }
    }
}

// ===========================================================================
// Kernel 2: flash-attention style. Per chunk:
//   S = U.Hc^T (mma fp16, K56), e = ex2(s) packed to fp16 A-frags,
//   G += E.Hc (B via ldmatrix.trans from the SAME smem tile).
// d = G[:,50] (ones column). Final: n = o.G, sigmoid. No per-chunk scalar
// accumulation, no tail special-case (zero H rows mask w>=1000).
// ===========================================================================
#define ROWB 144    // 72 halves per smem row: conflict-free 16B phases

#define MMA_F16(C, A0, A1, A2, A3, B0, B1)                                  \
    asm volatile(                                                           \
        "mma.sync.aligned.m16n8k16.row.col.f32.f16.f16.f32 "                \
        "{%0,%1,%2,%3}, {%4,%5,%6,%7}, {%8,%9}, {%0,%1,%2,%3};"             \
        : "+f"((C)[0]), "+f"((C)[1]), "+f"((C)[2]), "+f"((C)[3])            \
        : "r"(A0), "r"(A1), "r"(A2), "r"(A3), "r"(B0), "r"(B1))

#define MMA_F16K8(C, A0, A1, B0)                                            \
    asm volatile(                                                           \
        "mma.sync.aligned.m16n8k8.row.col.f32.f16.f16.f32 "                 \
        "{%0,%1,%2,%3}, {%4,%5}, {%6}, {%0,%1,%2,%3};"                      \
        : "+f"((C)[0]), "+f"((C)[1]), "+f"((C)[2]), "+f"((C)[3])            \
        : "r"(A0), "r"(A1), "r"(B0))

#define LDSM_X4(R, A)                                                       \
    asm volatile("ldmatrix.sync.aligned.m8n8.x4.shared.b16 "                \
                 "{%0,%1,%2,%3}, [%4];"                                     \
                 : "=r"((R)[0]), "=r"((R)[1]), "=r"((R)[2]), "=r"((R)[3])   \
                 : "r"(A))

#define LDSM_X4_T(R, A)                                                     \
    asm volatile("ldmatrix.sync.aligned.m8n8.x4.trans.shared.b16 "          \
                 "{%0,%1,%2,%3}, [%4];"                                     \
                 : "=r"((R)[0]), "=r"((R)[1]), "=r"((R)[2]), "=r"((R)[3])   \
                 : "r"(A))

#define LDSM_X2_T(R, A)                                                     \
    asm volatile("ldmatrix.sync.aligned.m8n8.x2.trans.shared.b16 "          \
                 "{%0,%1}, [%2];"                                           \
                 : "=r"((R)[0]), "=r"((R)[1]) : "r"(A))

#define CP_ASYNC16(S, G)                                                    \
    asm volatile("cp.async.cg.shared.global [%0], [%1], 16;"                \
                 :: "r"(S), "l"(G))
#define CP_COMMIT()  asm volatile("cp.async.commit_group;" ::: "memory")
#define CP_WAIT1()   asm volatile("cp.async.wait_group 1;" ::: "memory")
#define CP_WAIT0()   asm volatile("cp.async.wait_group 0;" ::: "memory")

__device__ __forceinline__ uint32_t packh2(float lo, float hi) {
    __half2 h = __floats2half2_rn(lo, hi);
    return *(uint32_t*)&h;
}
__device__ __forceinline__ float ex2f(float x) {
    float y;
    asm("ex2.approx.f32 %0, %1;" : "=f"(y) : "f"(x));
    return y;
}
__device__ __forceinline__ uint32_t cvta_smem(const void* p) {
    uint32_t a;
    asm("{ .reg .u64 t; cvta.to.shared.u64 t, %1; cvt.u32.u64 %0, t; }"
        : "=r"(a) : "l"(p));
    return a;
}

// S-GEMM (16 MMAs) -> e=ex2(s) as fp16 A-frags -> G-GEMM (14 MMAs, B via
// ldmatrix.trans from the same buffer).
__device__ __forceinline__ void compute_chunk(
    uint32_t sbase, int lane,
    const uint32_t uA[3][4], const uint32_t uA3[2],
    float G[7][4]) {
    const uint32_t aS = sbase + lane * ROWB;
    const uint32_t aT = sbase + (lane & 15) * ROWB + (lane >> 4) * 16;
    const uint32_t aT2 = sbase + (lane & 15) * ROWB + 96;

    float sacc[4][4];
#pragma unroll
    for (int nf = 0; nf < 4; nf++)
#pragma unroll
        for (int c = 0; c < 4; c++) sacc[nf][c] = 0.f;

#pragma unroll
    for (int ks = 0; ks < 3; ks++) {
        uint32_t b0v[4], b1v[4];
        LDSM_X4(b0v, aS + ks * 32);
        LDSM_X4(b1v, aS + ks * 32 + 16);
#pragma unroll
        for (int nf = 0; nf < 4; nf++)
            MMA_F16(sacc[nf], uA[ks][0], uA[ks][1], uA[ks][2], uA[ks][3],
                    b0v[nf], b1v[nf]);
    }
    {
        uint32_t bt[4];
        LDSM_X4(bt, aS + 96);
#pragma unroll
        for (int nf = 0; nf < 4; nf++)
            MMA_F16K8(sacc[nf], uA3[0], uA3[1], bt[nf]);
    }

    // e = exp(s) packed into m16k16 A fragments (C-frag layout == A-frag layout)
    uint32_t E[2][4];
#pragma unroll
    for (int hk = 0; hk < 2; hk++) {
        E[hk][0] = packh2(ex2f(sacc[2 * hk][0]),     ex2f(sacc[2 * hk][1]));
        E[hk][1] = packh2(ex2f(sacc[2 * hk][2]),     ex2f(sacc[2 * hk][3]));
        E[hk][2] = packh2(ex2f(sacc[2 * hk + 1][0]), ex2f(sacc[2 * hk + 1][1]));
        E[hk][3] = packh2(ex2f(sacc[2 * hk + 1][2]), ex2f(sacc[2 * hk + 1][3]));
    }

    // G += E . Hc   (k = w dim, n = c dim; c0..55, col 50 = ones -> d)
#pragma unroll
    for (int hk = 0; hk < 2; hk++) {
        const uint32_t aTh = aT + hk * 16 * ROWB;
#pragma unroll
        for (int cg = 0; cg < 3; cg++) {
            uint32_t bq[4];
            LDSM_X4_T(bq, aTh + cg * 32);
            MMA_F16(G[2 * cg],     E[hk][0], E[hk][1], E[hk][2], E[hk][3],
                    bq[0], bq[1]);
            MMA_F16(G[2 * cg + 1], E[hk][0], E[hk][1], E[hk][2], E[hk][3],
                    bq[2], bq[3]);
        }
        uint32_t b2[2];
        LDSM_X2_T(b2, aT2 + hk * 16 * ROWB);
        MMA_F16(G[6], E[hk][0], E[hk][1], E[hk][2], E[hk][3], b2[0], b2[1]);
    }
}

__global__ __launch_bounds__(128, 5)
void attn_kernel(const float* __restrict__ u_w, const float* __restrict__ out_w,
                 const float* __restrict__ out_b, float* __restrict__ out) {
    __shared__ __align__(16) uint32_t Hs[3][32 * 36];   // 3 x 4608B ring

    const int tid  = threadIdx.x;
    const int b    = blockIdx.y;
    const int l0   = blockIdx.x * 64;
    const int lane = tid & 31;
    const int wid  = tid >> 5;          // 0..3 label groups
    const int gid  = lane >> 2;
    const int tig  = lane & 3;

    // ---- Hoisted U fragments (pre-scaled by log2 e); K56
    const float LOG2E = 1.4426950408889634f;
    uint32_t uA[3][4], uA3[2];
#pragma unroll
    for (int ks = 0; ks < 3; ks++)
#pragma unroll
        for (int h = 0; h < 2; h++) {
            int kp = ks * 8 + tig + h * 4;
#pragma unroll
            for (int mo = 0; mo < 2; mo++) {
                int l = l0 + wid * 16 + gid + mo * 8;
                float2 uv = make_float2(0.f, 0.f);
                if (l < LL) uv = *(const float2*)&u_w[l * CC + 2 * kp];
                uA[ks][h * 2 + mo] = packh2(uv.x * LOG2E, uv.y * LOG2E);
            }
        }
    {
        int kp = 24 + tig;   // only kp 24 (k48,49) non-zero
#pragma unroll
        for (int mo = 0; mo < 2; mo++) {
            int l = l0 + wid * 16 + gid + mo * 8;
            float u0 = 0.f, u1 = 0.f;
            if (l < LL && kp == 24) {
                u0 = u_w[l * CC + 48]; u1 = u_w[l * CC + 49];
            }
            uA3[mo] = packh2(u0 * LOG2E, u1 * LOG2E);
        }
    }

    // ---- cp.async loader: 128 threads x 2 x 16B = 32 rows x 128B per chunk
    const int lrow = tid >> 2;             // 0..31
    const int lseg = (tid & 3) * 2;        // 0,2,4,6
    const uint32_t* gsrc = g_Hh + (b * WPAD + lrow) * 32 + lseg * 4;
    const uint32_t sb0 = cvta_smem(&Hs[0][0]);
    const uint32_t sb1 = cvta_smem(&Hs[1][0]);
    const uint32_t sb2 = cvta_smem(&Hs[2][0]);
    const uint32_t stoff = lrow * ROWB + lseg * 16;

#define ISSUE_CHUNK(s, dbase)                                                \
    do {                                                                     \
        const uint32_t* g_ = gsrc + (s) * 32 * 32;                           \
        uint32_t d_ = (dbase) + stoff;                                       \
        CP_ASYNC16(d_,      g_);                                             \
        CP_ASYNC16(d_ + 16, g_ + 4);                                         \
        CP_COMMIT();                                                         \
    } while (0)

    ISSUE_CHUNK(0, sb0);
    ISSUE_CHUNK(1, sb1);
    CP_WAIT1();
    __syncthreads();

    float G[7][4];
#pragma unroll
    for (int nf = 0; nf < 7; nf++)
#pragma unroll
        for (int c = 0; c < 4; c++) G[nf][c] = 0.f;

    // ---- main loop: chunks 0..29, x3-unrolled (static ring buffer indices)
#pragma unroll 1
    for (int ch = 0; ch < 30; ch += 3) {
        ISSUE_CHUNK(ch + 2, sb2);
        compute_chunk(sb0, lane, uA, uA3, G);
        CP_WAIT1();
        __syncthreads();

        ISSUE_CHUNK(ch + 3, sb0);
        compute_chunk(sb1, lane, uA, uA3, G);
        CP_WAIT1();
        __syncthreads();

        ISSUE_CHUNK(ch + 4, sb1);
        compute_chunk(sb2, lane, uA, uA3, G);
        CP_WAIT1();
        __syncthreads();
    }
    // chunk 30 (sb0) ready; chunk 31 (sb1) pending
    compute_chunk(sb0, lane, uA, uA3, G);
    CP_WAIT0();
    __syncthreads();
    compute_chunk(sb1, lane, uA, uA3, G);   // w>=1000 rows are zero: harmless

    // ---- final: n = o.G over c<50; d = G[:,50] (held by tig==1 in G[6][2r])
    float pn[2] = {0.f, 0.f};
#pragma unroll
    for (int r = 0; r < 2; r++) {
        int l = l0 + wid * 16 + gid + r * 8;
        bool lv = (l < LL);
        const float* orow = out_w + (long)(lv ? l : 0) * CC;
#pragma unroll
        for (int nf = 0; nf < 7; nf++)
#pragma unroll
            for (int j = 0; j < 2; j++) {
                int c = 8 * nf + 2 * tig + j;
                float ow = (lv && c < CC) ? orow[c] : 0.f;
                pn[r] = fmaf(ow, G[nf][2 * r + j], pn[r]);
            }
    }
    float dv[2];
#pragma unroll
    for (int r = 0; r < 2; r++) {
        dv[r] = __shfl_sync(0xffffffffu, G[6][2 * r], (lane & 0x1C) | 1);
        pn[r] += __shfl_xor_sync(0xffffffffu, pn[r], 1);
        pn[r] += __shfl_xor_sync(0xffffffffu, pn[r], 2);
    }
    if (tig == 0) {
#pragma unroll
        for (int r = 0; r < 2; r++) {
            int l = l0 + wid * 16 + gid + r * 8;
            if (l < LL) {
                float z = pn[r] / dv[r] + out_b[l];
                out[b * LL + l] = 1.f / (1.f + __expf(-z));
            }
        }
    }
}

// ===========================================================================
extern "C" void kernel_launch(void* const* d_in, const int* in_sizes, int n_in,
                              void* d_out, int out_size) {
    const int*   x       = (const int*)  d_in[0];
    const float* W_embed = (const float*)d_in[1];
    const float* conv_w  = (const float*)d_in[2];
    const float* conv_b  = (const float*)d_in[3];
    const float* u_w     = (const float*)d_in[4];
    const float* out_w   = (const float*)d_in[5];
    const float* out_b   = (const float*)d_in[6];
    float* out = (float*)d_out;

    dim3 cgrid(WLEN / CT_W, BB);          // (25, 8)
    conv_kernel<<<cgrid, 256>>>(x, W_embed, conv_w, conv_b);

    dim3 agrid((LL + 63) / 64, BB);       // (282, 8)
    attn_kernel<<<agrid, 128>>>(u_w, out_w, out_b, out);
}

// round 17
// speedup vs baseline: 1.0736x; 1.0736x over previous
#include <cuda_runtime.h>
#include <cuda_fp16.h>
#include <math.h>
#include <stdint.h>

#define BB   8
#define WLEN 1000
#define EMB  100
#define CC   50
#define LL   18000

#define WPAD 1024
// H: [b][w][k-halves], 64 halves (128B) per w row.
// k>=52 and w>=1000 stay zero; k50 = 1.0 (ones column for d), k51 = 0.
__device__ __align__(16) uint32_t g_Hh[BB * WPAD * 32];

// ===========================================================================
// Kernel 1: embedding + conv1d(k=3,same) + tanh -> g_Hh[b][w][k]
// swizzled emb_s: conflict-free LDS/STS. Also writes ones column at k=50.
// ===========================================================================
#define CT_W    40
#define CT_ROWS (CT_W + 2)

__device__ __forceinline__ float tanh_fast(float x) {
    float y;
    asm("tanh.approx.f32 %0, %1;" : "=f"(y) : "f"(x));
    return y;
}

__global__ __launch_bounds__(256)
void conv_kernel(const int* __restrict__ x, const float* __restrict__ W_embed,
                 const float* __restrict__ conv_w, const float* __restrict__ conv_b) {
    __shared__ __align__(16) float emb_s[CT_ROWS * 128];
    __shared__ int tok_s[CT_ROWS];
    const int b  = blockIdx.y;
    const int w0 = blockIdx.x * CT_W;
    const int tid = threadIdx.x;

    if (tid < CT_ROWS) {
        int w = w0 - 1 + tid;
        tok_s[tid] = (w >= 0 && w < WLEN) ? x[b * WLEN + w] : -1;
    }
    __syncthreads();
    for (int i = tid; i < CT_ROWS * 25; i += 256) {
        int r = i / 25, g = i - r * 25;
        int t = tok_s[r];
        float4 v = make_float4(0.f, 0.f, 0.f, 0.f);
        if (t >= 0) v = *(const float4*)&W_embed[(long)t * EMB + g * 4];
        *(float4*)&emb_s[(r * 32 + (g ^ ((r >> 2) & 7))) * 4] = v;
    }
    __syncthreads();

    if (tid < 250) {
        const int p = tid / 10, q = tid - p * 10;
        const int wl = q * 4;
        const int sw0 = q & 7, sw1 = (q + 1) & 7;
        const int c0 = 2 * p, c1 = 2 * p + 1;
        float acc[2][4];
        float bias0 = conv_b[c0], bias1 = conv_b[c1];
#pragma unroll
        for (int w = 0; w < 4; w++) { acc[0][w] = bias0; acc[1][w] = bias1; }

        const float4* cw0 = (const float4*)(conv_w + c0 * EMB * 3);
        const float4* cw1 = (const float4*)(conv_w + c1 * EMB * 3);

        for (int g = 0; g < 25; g++) {
            float4 v[6];
#pragma unroll
            for (int r = 0; r < 6; r++) {
                int sw = (r < 4) ? sw0 : sw1;
                v[r] = *(const float4*)&emb_s[((wl + r) * 32 + (g ^ sw)) * 4];
            }
            float4 q0 = cw0[g * 3], q1 = cw0[g * 3 + 1], q2 = cw0[g * 3 + 2];
#pragma unroll
            for (int w = 0; w < 4; w++) {
                acc[0][w] = fmaf(v[w].x, q0.x, acc[0][w]);
                acc[0][w] = fmaf(v[w + 1].x, q0.y, acc[0][w]);
                acc[0][w] = fmaf(v[w + 2].x, q0.z, acc[0][w]);
                acc[0][w] = fmaf(v[w].y, q0.w, acc[0][w]);
                acc[0][w] = fmaf(v[w + 1].y, q1.x, acc[0][w]);
                acc[0][w] = fmaf(v[w + 2].y, q1.y, acc[0][w]);
                acc[0][w] = fmaf(v[w].z, q1.z, acc[0][w]);
                acc[0][w] = fmaf(v[w + 1].z, q1.w, acc[0][w]);
                acc[0][w] = fmaf(v[w + 2].z, q2.x, acc[0][w]);
                acc[0][w] = fmaf(v[w].w, q2.y, acc[0][w]);
                acc[0][w] = fmaf(v[w + 1].w, q2.z, acc[0][w]);
                acc[0][w] = fmaf(v[w + 2].w, q2.w, acc[0][w]);
            }
            q0 = cw1[g * 3]; q1 = cw1[g * 3 + 1]; q2 = cw1[g * 3 + 2];
#pragma unroll
            for (int w = 0; w < 4; w++) {
                acc[1][w] = fmaf(v[w].x, q0.x, acc[1][w]);
                acc[1][w] = fmaf(v[w + 1].x, q0.y, acc[1][w]);
                acc[1][w] = fmaf(v[w + 2].x, q0.z, acc[1][w]);
                acc[1][w] = fmaf(v[w].y, q0.w, acc[1][w]);
                acc[1][w] = fmaf(v[w + 1].y, q1.x, acc[1][w]);
                acc[1][w] = fmaf(v[w + 2].y, q1.y, acc[1][w]);
                acc[1][w] = fmaf(v[w].z, q1.z, acc[1][w]);
                acc[1][w] = fmaf(v[w + 1].z, q1.w, acc[1][w]);
                acc[1][w] = fmaf(v[w + 2].z, q2.x, acc[1][w]);
                acc[1][w] = fmaf(v[w].w, q2.y, acc[1][w]);
                acc[1][w] = fmaf(v[w + 1].w, q2.z, acc[1][w]);
                acc[1][w] = fmaf(v[w + 2].w, q2.w, acc[1][w]);
            }
        }
#pragma unroll
        for (int i = 0; i < 4; i++) {
            __half2 h = __floats2half2_rn(tanh_fast(acc[0][i]), tanh_fast(acc[1][i]));
            g_Hh[((b * WPAD) + w0 + wl + i) * 32 + p] = *(uint32_t*)&h;
        }
        if (p == 0) {   // ones column: k50 = 1.0 (half 0x3C00), k51 = 0
#pragma unroll
            for (int i = 0; i < 4; i++)
                g_Hh[((b * WPAD) + w0 + wl + i) * 32 + 25] = 0x00003C00u;
        }
    }
}

// ===========================================================================
// Kernel 2: flash-attention style, CROSS-CHUNK pipelined:
//   iteration c interleaves S-GEMM(chunk c) with G-GEMM(chunk c-1) in
//   program order (independent MMA streams fill each other's gaps).
//   e = ex2.approx.f16x2 of packed s. 4-buffer cp.async ring.
// d = G[:,50] (ones column). Final: n = o.G, sigmoid.
// ===========================================================================
#define ROWB 144    // 72 halves per smem row: conflict-free 16B phases

#define MMA_F16(C, A0, A1, A2, A3, B0, B1)                                  \
    asm volatile(                                                           \
        "mma.sync.aligned.m16n8k16.row.col.f32.f16.f16.f32 "                \
        "{%0,%1,%2,%3}, {%4,%5,%6,%7}, {%8,%9}, {%0,%1,%2,%3};"             \
        : "+f"((C)[0]), "+f"((C)[1]), "+f"((C)[2]), "+f"((C)[3])            \
        : "r"(A0), "r"(A1), "r"(A2), "r"(A3), "r"(B0), "r"(B1))

#define MMA_F16K8(C, A0, A1, B0)                                            \
    asm volatile(                                                           \
        "mma.sync.aligned.m16n8k8.row.col.f32.f16.f16.f32 "                 \
        "{%0,%1,%2,%3}, {%4,%5}, {%6}, {%0,%1,%2,%3};"                      \
        : "+f"((C)[0]), "+f"((C)[1]), "+f"((C)[2]), "+f"((C)[3])            \
        : "r"(A0), "r"(A1), "r"(B0))

#define LDSM_X4(R, A)                                                       \
    asm volatile("ldmatrix.sync.aligned.m8n8.x4.shared.b16 "                \
                 "{%0,%1,%2,%3}, [%4];"                                     \
                 : "=r"((R)[0]), "=r"((R)[1]), "=r"((R)[2]), "=r"((R)[3])   \
                 : "r"(A))

#define LDSM_X4_T(R, A)                                                     \
    asm volatile("ldmatrix.sync.aligned.m8n8.x4.trans.shared.b16 "          \
                 "{%0,%1,%2,%3}, [%4];"                                     \
                 : "=r"((R)[0]), "=r"((R)[1]), "=r"((R)[2]), "=r"((R)[3])   \
                 : "r"(A))

#define LDSM_X2_T(R, A)                                                     \
    asm volatile("ldmatrix.sync.aligned.m8n8.x2.trans.shared.b16 "          \
                 "{%0,%1}, [%2];"                                           \
                 : "=r"((R)[0]), "=r"((R)[1]) : "r"(A))

#define CP_ASYNC16(S, G)                                                    \
    asm volatile("cp.async.cg.shared.global [%0], [%1], 16;"                \
                 :: "r"(S), "l"(G))
#define CP_COMMIT()  asm volatile("cp.async.commit_group;" ::: "memory")
#define CP_WAIT1()   asm volatile("cp.async.wait_group 1;" ::: "memory")
#define CP_WAIT0()   asm volatile("cp.async.wait_group 0;" ::: "memory")

__device__ __forceinline__ uint32_t packh2(float lo, float hi) {
    __half2 h = __floats2half2_rn(lo, hi);
    return *(uint32_t*)&h;
}
// e = 2^s on a packed fp16 pair: 1 CVT + 1 MUFU (replaces 2 MUFU + 1 CVT)
__device__ __forceinline__ uint32_t ex2_h2(float lo, float hi) {
    uint32_t p = packh2(lo, hi), r;
    asm("ex2.approx.f16x2 %0, %1;" : "=r"(r) : "r"(p));
    return r;
}
__device__ __forceinline__ uint32_t cvta_smem(const void* p) {
    uint32_t a;
    asm("{ .reg .u64 t; cvta.to.shared.u64 t, %1; cvt.u32.u64 %0, t; }"
        : "=r"(a) : "l"(p));
    return a;
}

// One pipeline step: S-GEMM on bufS (16 MMAs) interleaved instruction-by-
// instruction with G-GEMM on bufG using Ein (14 MMAs). Eout <- ex2(S).
template<bool DO_S, bool DO_G>
__device__ __forceinline__ void pipe_step(
    uint32_t bufS, uint32_t bufG, int lane,
    const uint32_t uA[3][4], const uint32_t uA3[2],
    const uint32_t Ein[2][4], uint32_t Eout[2][4], float G[7][4]) {
    const uint32_t aS  = bufS + lane * ROWB;
    const uint32_t aT  = bufG + (lane & 15) * ROWB + (lane >> 4) * 16;
    const uint32_t aT2 = bufG + (lane & 15) * ROWB + 96;

    float sacc[4][4];
    if (DO_S) {
#pragma unroll
        for (int nf = 0; nf < 4; nf++)
#pragma unroll
            for (int c = 0; c < 4; c++) sacc[nf][c] = 0.f;
    }

    uint32_t sb0[4], sb1[4];
    uint32_t ta[4], tb[4], t2[2];

    // -- phase 0: S ks0 loads + G hk0 cg0/cg1 loads
    if (DO_S) { LDSM_X4(sb0, aS);      LDSM_X4(sb1, aS + 16); }
    if (DO_G) { LDSM_X4_T(ta, aT);     LDSM_X4_T(tb, aT + 32); }
    if (DO_S) {
#pragma unroll
        for (int nf = 0; nf < 4; nf++)
            MMA_F16(sacc[nf], uA[0][0], uA[0][1], uA[0][2], uA[0][3],
                    sb0[nf], sb1[nf]);
    }
    if (DO_G) {
        MMA_F16(G[0], Ein[0][0], Ein[0][1], Ein[0][2], Ein[0][3], ta[0], ta[1]);
        MMA_F16(G[1], Ein[0][0], Ein[0][1], Ein[0][2], Ein[0][3], ta[2], ta[3]);
        MMA_F16(G[2], Ein[0][0], Ein[0][1], Ein[0][2], Ein[0][3], tb[0], tb[1]);
        MMA_F16(G[3], Ein[0][0], Ein[0][1], Ein[0][2], Ein[0][3], tb[2], tb[3]);
    }

    // -- phase 1: S ks1 + G hk0 cg2 / ones
    if (DO_S) { LDSM_X4(sb0, aS + 32); LDSM_X4(sb1, aS + 48); }
    if (DO_G) { LDSM_X4_T(ta, aT + 64); LDSM_X2_T(t2, aT2); }
    if (DO_S) {
#pragma unroll
        for (int nf = 0; nf < 4; nf++)
            MMA_F16(sacc[nf], uA[1][0], uA[1][1], uA[1][2], uA[1][3],
                    sb0[nf], sb1[nf]);
    }
    if (DO_G) {
        MMA_F16(G[4], Ein[0][0], Ein[0][1], Ein[0][2], Ein[0][3], ta[0], ta[1]);
        MMA_F16(G[5], Ein[0][0], Ein[0][1], Ein[0][2], Ein[0][3], ta[2], ta[3]);
        MMA_F16(G[6], Ein[0][0], Ein[0][1], Ein[0][2], Ein[0][3], t2[0], t2[1]);
    }

    // -- phase 2: S ks2 + G hk1 cg0/cg1
    if (DO_S) { LDSM_X4(sb0, aS + 64); LDSM_X4(sb1, aS + 80); }
    if (DO_G) { LDSM_X4_T(ta, aT + 16 * ROWB); LDSM_X4_T(tb, aT + 16 * ROWB + 32); }
    if (DO_S) {
#pragma unroll
        for (int nf = 0; nf < 4; nf++)
            MMA_F16(sacc[nf], uA[2][0], uA[2][1], uA[2][2], uA[2][3],
                    sb0[nf], sb1[nf]);
    }
    if (DO_G) {
        MMA_F16(G[0], Ein[1][0], Ein[1][1], Ein[1][2], Ein[1][3], ta[0], ta[1]);
        MMA_F16(G[1], Ein[1][0], Ein[1][1], Ein[1][2], Ein[1][3], ta[2], ta[3]);
        MMA_F16(G[2], Ein[1][0], Ein[1][1], Ein[1][2], Ein[1][3], tb[0], tb[1]);
        MMA_F16(G[3], Ein[1][0], Ein[1][1], Ein[1][2], Ein[1][3], tb[2], tb[3]);
    }

    // -- phase 3: S k8 tail + G hk1 cg2 / ones
    if (DO_S) { LDSM_X4(sb0, aS + 96); }
    if (DO_G) { LDSM_X4_T(ta, aT + 16 * ROWB + 64); LDSM_X2_T(t2, aT2 + 16 * ROWB); }
    if (DO_S) {
#pragma unroll
        for (int nf = 0; nf < 4; nf++)
            MMA_F16K8(sacc[nf], uA3[0], uA3[1], sb0[nf]);
    }
    if (DO_G) {
        MMA_F16(G[4], Ein[1][0], Ein[1][1], Ein[1][2], Ein[1][3], ta[0], ta[1]);
        MMA_F16(G[5], Ein[1][0], Ein[1][1], Ein[1][2], Ein[1][3], ta[2], ta[3]);
        MMA_F16(G[6], Ein[1][0], Ein[1][1], Ein[1][2], Ein[1][3], t2[0], t2[1]);
    }

    // -- Eout = ex2(S) as fp16x2 A-fragments
    if (DO_S) {
#pragma unroll
        for (int hk = 0; hk < 2; hk++) {
            Eout[hk][0] = ex2_h2(sacc[2 * hk][0],     sacc[2 * hk][1]);
            Eout[hk][1] = ex2_h2(sacc[2 * hk][2],     sacc[2 * hk][3]);
            Eout[hk][2] = ex2_h2(sacc[2 * hk + 1][0], sacc[2 * hk + 1][1]);
            Eout[hk][3] = ex2_h2(sacc[2 * hk + 1][2], sacc[2 * hk + 1][3]);
        }
    }
}

__global__ __launch_bounds__(128, 5)
void attn_kernel(const float* __restrict__ u_w, const float* __restrict__ out_w,
                 const float* __restrict__ out_b, float* __restrict__ out) {
    __shared__ __align__(16) uint32_t Hs[4][32 * 36];   // 4 x 4608B ring

    const int tid  = threadIdx.x;
    const int b    = blockIdx.y;
    const int l0   = blockIdx.x * 64;
    const int lane = tid & 31;
    const int wid  = tid >> 5;          // 0..3 label groups
    const int gid  = lane >> 2;
    const int tig  = lane & 3;

    // ---- Hoisted U fragments (pre-scaled by log2 e); K56
    const float LOG2E = 1.4426950408889634f;
    uint32_t uA[3][4], uA3[2];
#pragma unroll
    for (int ks = 0; ks < 3; ks++)
#pragma unroll
        for (int h = 0; h < 2; h++) {
            int kp = ks * 8 + tig + h * 4;
#pragma unroll
            for (int mo = 0; mo < 2; mo++) {
                int l = l0 + wid * 16 + gid + mo * 8;
                float2 uv = make_float2(0.f, 0.f);
                if (l < LL) uv = *(const float2*)&u_w[l * CC + 2 * kp];
                uA[ks][h * 2 + mo] = packh2(uv.x * LOG2E, uv.y * LOG2E);
            }
        }
    {
        int kp = 24 + tig;   // only kp 24 (k48,49) non-zero
#pragma unroll
        for (int mo = 0; mo < 2; mo++) {
            int l = l0 + wid * 16 + gid + mo * 8;
            float u0 = 0.f, u1 = 0.f;
            if (l < LL && kp == 24) {
                u0 = u_w[l * CC + 48]; u1 = u_w[l * CC + 49];
            }
            uA3[mo] = packh2(u0 * LOG2E, u1 * LOG2E);
        }
    }

    // ---- cp.async loader: 128 threads x 2 x 16B = 32 rows x 128B per chunk
    const int lrow = tid >> 2;             // 0..31
    const int lseg = (tid & 3) * 2;        // 0,2,4,6
    const uint32_t* gsrc = g_Hh + (b * WPAD + lrow) * 32 + lseg * 4;
    const uint32_t sb0 = cvta_smem(&Hs[0][0]);
    const uint32_t sb1 = cvta_smem(&Hs[1][0]);
    const uint32_t sb2 = cvta_smem(&Hs[2][0]);
    const uint32_t sb3 = cvta_smem(&Hs[3][0]);
    const uint32_t stoff = lrow * ROWB + lseg * 16;

#define ISSUE_CHUNK(s, dbase)                                                \
    do {                                                                     \
        const uint32_t* g_ = gsrc + (s) * 32 * 32;                           \
        uint32_t d_ = (dbase) + stoff;                                       \
        CP_ASYNC16(d_,      g_);                                             \
        CP_ASYNC16(d_ + 16, g_ + 4);                                         \
        CP_COMMIT();                                                         \
    } while (0)

    ISSUE_CHUNK(0, sb0);
    ISSUE_CHUNK(1, sb1);
    CP_WAIT1();
    __syncthreads();

    float G[7][4];
#pragma unroll
    for (int nf = 0; nf < 7; nf++)
#pragma unroll
        for (int c = 0; c < 4; c++) G[nf][c] = 0.f;
    uint32_t Ea[2][4], Eb[2][4];

    // ---- iter 0: S(0) only
    ISSUE_CHUNK(2, sb2);
    pipe_step<true, false>(sb0, sb0, lane, uA, uA3, Ea, Ea, G);
    CP_WAIT1();
    __syncthreads();

    // ---- iters 1..28 (x4-unrolled, static ring/E-buffer names)
    // iter c: issue c+2 into (c+2)%4; S(c) from c%4; G(c-1) from (c-1)%4.
#pragma unroll 1
    for (int c = 1; c <= 25; c += 4) {
        ISSUE_CHUNK(c + 2, sb3);
        pipe_step<true, true>(sb1, sb0, lane, uA, uA3, Ea, Eb, G);
        CP_WAIT1(); __syncthreads();

        ISSUE_CHUNK(c + 3, sb0);
        pipe_step<true, true>(sb2, sb1, lane, uA, uA3, Eb, Ea, G);
        CP_WAIT1(); __syncthreads();

        ISSUE_CHUNK(c + 4, sb1);
        pipe_step<true, true>(sb3, sb2, lane, uA, uA3, Ea, Eb, G);
        CP_WAIT1(); __syncthreads();

        ISSUE_CHUNK(c + 5, sb2);
        pipe_step<true, true>(sb0, sb3, lane, uA, uA3, Eb, Ea, G);
        CP_WAIT1(); __syncthreads();
    }

    // ---- iter 29: S(29)=sb1, G(28)=sb0, issue 31 -> sb3
    ISSUE_CHUNK(31, sb3);
    pipe_step<true, true>(sb1, sb0, lane, uA, uA3, Ea, Eb, G);
    CP_WAIT1(); __syncthreads();

    // ---- iter 30: S(30)=sb2, G(29)=sb1; drain all pending copies
    pipe_step<true, true>(sb2, sb1, lane, uA, uA3, Eb, Ea, G);
    CP_WAIT0(); __syncthreads();

    // ---- iter 31: S(31)=sb3, G(30)=sb2 (read-only from here; no barrier)
    pipe_step<true, true>(sb3, sb2, lane, uA, uA3, Ea, Eb, G);

    // ---- epilogue: G(31)=sb3  (w>=1000 rows are zero: contributions vanish)
    pipe_step<false, true>(sb3, sb3, lane, uA, uA3, Eb, Ea, G);

    // ---- final: n = o.G over c<50; d = G[:,50] (tig==1 holds it in G[6][2r])
    float pn[2] = {0.f, 0.f};
#pragma unroll
    for (int r = 0; r < 2; r++) {
        int l = l0 + wid * 16 + gid + r * 8;
        bool lv = (l < LL);
        const float* orow = out_w + (long)(lv ? l : 0) * CC;
#pragma unroll
        for (int nf = 0; nf < 7; nf++)
#pragma unroll
            for (int j = 0; j < 2; j++) {
                int c = 8 * nf + 2 * tig + j;
                float ow = (lv && c < CC) ? orow[c] : 0.f;
                pn[r] = fmaf(ow, G[nf][2 * r + j], pn[r]);
            }
    }
    float dv[2];
#pragma unroll
    for (int r = 0; r < 2; r++) {
        dv[r] = __shfl_sync(0xffffffffu, G[6][2 * r], (lane & 0x1C) | 1);
        pn[r] += __shfl_xor_sync(0xffffffffu, pn[r], 1);
        pn[r] += __shfl_xor_sync(0xffffffffu, pn[r], 2);
    }
    if (tig == 0) {
#pragma unroll
        for (int r = 0; r < 2; r++) {
            int l = l0 + wid * 16 + gid + r * 8;
            if (l < LL) {
                float z = pn[r] / dv[r] + out_b[l];
                out[b * LL + l] = 1.f / (1.f + __expf(-z));
            }
        }
    }
}

// ===========================================================================
extern "C" void kernel_launch(void* const* d_in, const int* in_sizes, int n_in,
                              void* d_out, int out_size) {
    const int*   x       = (const int*)  d_in[0];
    const float* W_embed = (const float*)d_in[1];
    const float* conv_w  = (const float*)d_in[2];
    const float* conv_b  = (const float*)d_in[3];
    const float* u_w     = (const float*)d_in[4];
    const float* out_w   = (const float*)d_in[5];
    const float* out_b   = (const float*)d_in[6];
    float* out = (float*)d_out;

    dim3 cgrid(WLEN / CT_W, BB);          // (25, 8)
    conv_kernel<<<cgrid, 256>>>(x, W_embed, conv_w, conv_b);

    dim3 agrid((LL + 63) / 64, BB);       // (282, 8)
    attn_kernel<<<agrid, 128>>>(u_w, out_w, out_b, out);
}